// round 17
// baseline (speedup 1.0000x reference)
#include <cuda_runtime.h>
#include <cuda_fp16.h>

#define BATCH   4096
#define FEAT    40960
#define ACCUM   512
#define H1      32
#define MAXIDX  128

// Scratch (device globals — no allocations allowed)
__device__ __half g_ftTh[(size_t)FEAT * ACCUM];   // transposed fp16 weights [FEAT][ACCUM] (42 MB, L2-resident)
__device__ int    g_stm_mode;                     // 0 = byte bool, 1 = int32, 2 = float32

// ---------------------------------------------------------------------------
// K1: transpose + fp32->fp16 convert, CHUNKED (unchanged from R16 winner).
// ---------------------------------------------------------------------------
__global__ __launch_bounds__(512) void transpose_kernel(
    const float* __restrict__ ftw,
    const unsigned char* __restrict__ stm)
{
    __shared__ float tile[64][33];
    __shared__ int bad_int, bad_f32;

    const int t = threadIdx.x;
    const bool detect = (blockIdx.x == 0 && blockIdx.y == 0);

    if (detect) {
        if (t == 0) { bad_int = 0; bad_f32 = 0; }
        __syncthreads();
        for (int g = t; g < 1024; g += 512) {
            unsigned char b0 = stm[4*g+0], b1 = stm[4*g+1];
            unsigned char b2 = stm[4*g+2], b3 = stm[4*g+3];
            if (!((b1 | b2 | b3) == 0 && b0 <= 1)) atomicOr(&bad_int, 1);
            bool zero = (b0 | b1 | b2 | b3) == 0;
            bool one  = (b0 == 0 && b1 == 0 && b2 == 0x80 && b3 == 0x3F);
            if (!(zero || one)) atomicOr(&bad_f32, 1);
        }
        __syncthreads();
        if (t == 0)
            g_stm_mode = (!bad_int) ? 1 : ((!bad_f32) ? 2 : 0);
        __syncthreads();
    }

    const int fx  = blockIdx.x * 64;          // feature stripe origin
    const int oy0 = blockIdx.y * 256;         // accum range origin (8 x 32)

    const int a = t >> 4, q = t & 15;         // load indexing
    const int f = t >> 2, qq = t & 3;         // store indexing (t < 256)

    float4 v = __ldcs((const float4*)&ftw[(size_t)(oy0 + a) * FEAT + fx + 4*q]);

    #pragma unroll
    for (int i = 0; i < 8; i++) {
        const int oy = oy0 + i * 32;

        tile[4*q + 0][a] = v.x;
        tile[4*q + 1][a] = v.y;
        tile[4*q + 2][a] = v.z;
        tile[4*q + 3][a] = v.w;
        __syncthreads();

        if (i < 7)
            v = __ldcs((const float4*)&ftw[(size_t)(oy + 32 + a) * FEAT + fx + 4*q]);

        if (t < 256) {
            __half2 h0 = __floats2half2_rn(tile[f][8*qq + 0], tile[f][8*qq + 1]);
            __half2 h1 = __floats2half2_rn(tile[f][8*qq + 2], tile[f][8*qq + 3]);
            __half2 h2 = __floats2half2_rn(tile[f][8*qq + 4], tile[f][8*qq + 5]);
            __half2 h3 = __floats2half2_rn(tile[f][8*qq + 6], tile[f][8*qq + 7]);
            uint4 o;
            o.x = *reinterpret_cast<unsigned*>(&h0);
            o.y = *reinterpret_cast<unsigned*>(&h1);
            o.z = *reinterpret_cast<unsigned*>(&h2);
            o.w = *reinterpret_cast<unsigned*>(&h3);
            *(uint4*)&g_ftTh[(size_t)(fx + f) * ACCUM + oy + 8*qq] = o;
        }
        __syncthreads();
    }
}

// ---------------------------------------------------------------------------
// Scan helper: one 20-iter fully-unrolled pass over a 40960-feature row.
// (forceinline -> shared-pointer provenance stays visible to ptxas)
// ---------------------------------------------------------------------------
__device__ __forceinline__ void scan_row(const float4* __restrict__ rowp,
                                         int* cnt, int* idx, int t)
{
    #pragma unroll
    for (int i = 0; i < FEAT / 4 / 512; i++) {
        int vi = t + i * 512;
        float4 v = __ldcs(&rowp[vi]);
        if (v.x != 0.f) { int p = atomicAdd(cnt, 1); if (p < MAXIDX) idx[p] = 4*vi + 0; }
        if (v.y != 0.f) { int p = atomicAdd(cnt, 1); if (p < MAXIDX) idx[p] = 4*vi + 1; }
        if (v.z != 0.f) { int p = atomicAdd(cnt, 1); if (p < MAXIDX) idx[p] = 4*vi + 2; }
        if (v.w != 0.f) { int p = atomicAdd(cnt, 1); if (p < MAXIDX) idx[p] = 4*vi + 3; }
    }
}

// Gather helper: 8 groups x 64 threads, 8 fp16 channels per thread per feature.
__device__ __forceinline__ void gather_row(int cnt, const int* idx,
                                           float (*sp)[ACCUM], int g, int u)
{
    float s0=0.f,s1=0.f,s2=0.f,s3=0.f,s4=0.f,s5=0.f,s6=0.f,s7=0.f;
    #pragma unroll 1
    for (int k = g; k < cnt; k += 8) {
        uint4 v = *(const uint4*)&g_ftTh[(size_t)idx[k] * ACCUM + 8*u];
        float2 f0 = __half22float2(*reinterpret_cast<__half2*>(&v.x));
        float2 f1 = __half22float2(*reinterpret_cast<__half2*>(&v.y));
        float2 f2 = __half22float2(*reinterpret_cast<__half2*>(&v.z));
        float2 f3 = __half22float2(*reinterpret_cast<__half2*>(&v.w));
        s0 += f0.x; s1 += f0.y; s2 += f1.x; s3 += f1.y;
        s4 += f2.x; s5 += f2.y; s6 += f3.x; s7 += f3.y;
    }
    sp[g][8*u + 0] = s0; sp[g][8*u + 1] = s1;
    sp[g][8*u + 2] = s2; sp[g][8*u + 3] = s3;
    sp[g][8*u + 4] = s4; sp[g][8*u + 5] = s5;
    sp[g][8*u + 6] = s6; sp[g][8*u + 7] = s7;
}

#define REDUCE8(sp) (((sp[0][t] + sp[1][t]) + (sp[2][t] + sp[3][t])) \
                   + ((sp[4][t] + sp[5][t]) + (sp[6][t] + sp[7][t])))

// ---------------------------------------------------------------------------
// K2: NNUE forward, TWO rows per block (grid 2048), 512 threads, 4 CTAs/SM.
// Chained overlap: every gather except the last hides under the next scan.
//   scanW0 | scanW1+gatherW0 | scanB0+gatherW1 | scanB1+gatherB0 | gatherB1
// sp double-buffered (A/B) so WAR hazards sit behind existing barriers.
// ---------------------------------------------------------------------------
__global__ __launch_bounds__(512, 4) void nnue_kernel(
    const float* __restrict__ wf, const float* __restrict__ bf,
    const unsigned char* __restrict__ stm_raw,
    const float* __restrict__ ft_b,
    const float* __restrict__ l1_w, const float* __restrict__ l1_b,
    const float* __restrict__ l2_w, const float* __restrict__ l2_b,
    const float* __restrict__ out_w, const float* __restrict__ out_b,
    float* __restrict__ out)
{
    const int r0 = blockIdx.x * 2;
    const int r1 = r0 + 1;
    const int t  = threadIdx.x;

    __shared__ float spA[8][ACCUM];            // 16 KB
    __shared__ float spB[8][ACCUM];            // 16 KB
    __shared__ int   idxw0[MAXIDX], idxb0[MAXIDX];
    __shared__ int   idxw1[MAXIDX], idxb1[MAXIDX];
    __shared__ int   nw0, nb0, nw1, nb1;
    __shared__ float x0[2 * ACCUM], x1[2 * ACCUM];   // 8 KB
    __shared__ float v1s[2][H1];

    if (t == 0) { nw0 = 0; nb0 = 0; nw1 = 0; nb1 = 0; }
    __syncthreads();

    const float4* w0p = (const float4*)(wf + (size_t)r0 * FEAT);
    const float4* w1p = (const float4*)(wf + (size_t)r1 * FEAT);
    const float4* b0p = (const float4*)(bf + (size_t)r0 * FEAT);
    const float4* b1p = (const float4*)(bf + (size_t)r1 * FEAT);

    const int g = t >> 6;        // gather group 0..7
    const int u = t & 63;        // channel octet

    // 1) scan W(r0)
    scan_row(w0p, &nw0, idxw0, t);
    __syncthreads();
    const int cw0 = min(nw0, MAXIDX);

    // 2) scan W(r1)  ||  gather W(r0) -> spA
    scan_row(w1p, &nw1, idxw1, t);
    gather_row(cw0, idxw0, spA, g, u);
    __syncthreads();
    const int cw1 = min(nw1, MAXIDX);

    // 3) scan B(r0)  ||  gather W(r1) -> spB  ||  reduce W(r0) from spA
    scan_row(b0p, &nb0, idxb0, t);
    gather_row(cw1, idxw1, spB, g, u);
    float accw0 = ft_b[t] + REDUCE8(spA);
    __syncthreads();
    const int cb0 = min(nb0, MAXIDX);

    // 4) scan B(r1)  ||  gather B(r0) -> spA  ||  reduce W(r1) from spB
    scan_row(b1p, &nb1, idxb1, t);
    gather_row(cb0, idxb0, spA, g, u);
    float accw1 = ft_b[t] + REDUCE8(spB);
    __syncthreads();
    const int cb1 = min(nb1, MAXIDX);

    // 5) gather B(r1) -> spB  ||  reduce B(r0) from spA
    gather_row(cb1, idxb1, spB, g, u);
    float accb0 = ft_b[t] + REDUCE8(spA);
    __syncthreads();

    // 6) reduce B(r1)
    float accb1 = ft_b[t] + REDUCE8(spB);

    // screlu
    accw0 = fminf(fmaxf(accw0, 0.f), 1.f); accw0 *= accw0;
    accw1 = fminf(fmaxf(accw1, 0.f), 1.f); accw1 *= accw1;
    accb0 = fminf(fmaxf(accb0, 0.f), 1.f); accb0 *= accb0;
    accb1 = fminf(fmaxf(accb1, 0.f), 1.f); accb1 *= accb1;

    // stm select (dtype-mode decoded), per row
    bool s0, s1;
    {
        int mode = g_stm_mode;
        if (mode == 1)      { s0 = ((const int*)stm_raw)[r0] != 0;   s1 = ((const int*)stm_raw)[r1] != 0; }
        else if (mode == 2) { s0 = ((const float*)stm_raw)[r0] != 0.f; s1 = ((const float*)stm_raw)[r1] != 0.f; }
        else                { s0 = stm_raw[r0] != 0;                 s1 = stm_raw[r1] != 0; }
    }
    x0[t]         = s0 ? accb0 : accw0;
    x0[ACCUM + t] = s0 ? accw0 : accb0;
    x1[t]         = s1 ? accb1 : accw1;
    x1[ACCUM + t] = s1 ? accw1 : accb1;
    __syncthreads();

    // ---- L1: warps 0-7 -> row r0 (4 outputs each), warps 8-15 -> row r1 ----
    const int warp = t >> 5, lane = t & 31;
    {
        const int   rsel = warp >> 3;              // 0 or 1
        const int   wloc = warp & 7;               // 0..7
        const float* xr  = rsel ? x1 : x0;
        #pragma unroll
        for (int oo = 0; oo < 4; oo++) {
            int o = wloc * 4 + oo;
            const float* w1 = l1_w + (size_t)o * (2 * ACCUM);
            float sum = 0.f;
            #pragma unroll
            for (int j = lane; j < 2 * ACCUM; j += 32)
                sum += xr[j] * __ldg(&w1[j]);
            #pragma unroll
            for (int off = 16; off > 0; off >>= 1)
                sum += __shfl_down_sync(0xffffffffu, sum, off);
            if (lane == 0) {
                sum += l1_b[o];
                sum = fminf(fmaxf(sum, 0.f), 1.f);
                v1s[rsel][o] = sum * sum;
            }
        }
    }
    __syncthreads();

    // ---- L2 layer + output head: warp 0 -> r0, warp 1 -> r1 ----
    if (warp < 2) {
        float sum = l2_b[lane];
        #pragma unroll
        for (int j = 0; j < H1; j++)
            sum += v1s[warp][j] * __ldg(&l2_w[lane * H1 + j]);
        sum = fminf(fmaxf(sum, 0.f), 1.f);
        float vv = sum * sum * __ldg(&out_w[lane]);
        #pragma unroll
        for (int off = 16; off > 0; off >>= 1)
            vv += __shfl_down_sync(0xffffffffu, vv, off);
        if (lane == 0) out[r0 + warp] = vv + out_b[0];
    }
}

// ---------------------------------------------------------------------------
extern "C" void kernel_launch(void* const* d_in, const int* in_sizes, int n_in,
                              void* d_out, int out_size) {
    const float*         wf    = (const float*)d_in[0];
    const float*         bf    = (const float*)d_in[1];
    const unsigned char* stm   = (const unsigned char*)d_in[2];
    const float*         ft_w  = (const float*)d_in[3];
    const float*         ft_b  = (const float*)d_in[4];
    const float*         l1_w  = (const float*)d_in[5];
    const float*         l1_b  = (const float*)d_in[6];
    const float*         l2_w  = (const float*)d_in[7];
    const float*         l2_b  = (const float*)d_in[8];
    const float*         out_w = (const float*)d_in[9];
    const float*         out_b = (const float*)d_in[10];
    float*               out   = (float*)d_out;

    dim3 tgrid(FEAT / 64, ACCUM / 256);   // (640, 2)
    transpose_kernel<<<tgrid, 512>>>(ft_w, stm);

    nnue_kernel<<<BATCH / 2, 512>>>(wf, bf, stm, ft_b, l1_w, l1_b,
                                    l2_w, l2_b, out_w, out_b, out);
}